// round 14
// baseline (speedup 1.0000x reference)
#include <cuda_runtime.h>

#define Nn 2048
#define Ee 65536

// ---------------- scratch (device globals; no allocations) ----------------
__device__ __align__(16) float g_feat[Nn*320];     // [x | h1 | h2]
__device__ __align__(16) float g_xW[Nn*128];       // 512B line-aligned rows
__device__ __align__(16) float g_xr[Nn];
__device__ __align__(16) float g_S[Nn*128];
__device__ __align__(16) float g_ab[Nn*40];
__device__ __align__(16) float g_W1p[40*320];
__device__ __align__(16) float g_B0p[129*64];
__device__ __align__(16) float g_B1p[129*128];
__device__ __align__(16) float g_w1e[256];
__device__ __align__(16) float2 g_edge[Ee];        // CSR payload: (src bits, edge_attr)
__device__ int g_deg[Nn];                          // invariant: zero (restored by scan)
__device__ int g_off[Nn+1];
__device__ int g_cur[Nn];

__device__ __forceinline__ float lrelu(float x) { return x > 0.f ? x : 0.01f*x; }

__device__ __forceinline__ float* sel_ptr(int s) {
  switch (s) {
    case 0: return g_feat;
    case 1: return g_S;
    case 2: return g_xW;
    case 3: return g_W1p;
    case 4: return g_B0p;
    case 5: return g_B1p;
    case 6: return g_ab;
    default: return nullptr;
  }
}

// ---------------- fused setup: embed(f4) + packs + hist ----------------
__global__ void k_setup(const int* __restrict__ ids, const float* __restrict__ emb,
                        const float* __restrict__ W1,
                        const float* __restrict__ l0_lin1, const float* __restrict__ l1_lin1,
                        const float* __restrict__ l0_attr, const float* __restrict__ l1_attr,
                        const int* __restrict__ edst) {
  int b = blockIdx.x, tid = threadIdx.x;
  if (b < 128) {                       // embedding -> feat cols 0..63, float4
    int node = b*16 + (tid >> 4);
    int c4 = tid & 15;
    ((float4*)g_feat)[node*80 + c4] = ((const float4*)emb)[ids[node]*16 + c4];
  } else if (b < 178) {
    int i = (b-128)*256 + tid;
    if (i < 40*320) {
      int r = i/320, c = i - r*320;
      g_W1p[i] = (r < 20) ? W1[r*640 + c] : W1[(r-20)*640 + 320 + c];
    }
  } else if (b == 178) {
    if (tid < 128) {
      g_w1e[tid]       = l0_lin1[tid*65  + 64];
      g_w1e[128 + tid] = l1_lin1[tid*129 + 128];
    }
  } else if (b < 213) {
    int i = (b-179)*256 + tid;
    if (i < 129*64) {
      int r = i >> 6, c = i & 63;
      g_B0p[i] = (r < 128) ? l0_lin1[r*65 + c] : l0_attr[c];
    }
  } else if (b < 278) {
    int i = (b-213)*256 + tid;
    if (i < 129*128) {
      int r = i >> 7, c = i & 127;
      g_B1p[i] = (r < 128) ? l1_lin1[r*129 + c] : l1_attr[c];
    }
  } else {
    int e = (b-278)*256 + tid;
    atomicAdd(&g_deg[edst[e]], 1);
  }
}

// ---------------- scan (256 threads), restores g_deg=0 ----------------
__device__ void dev_scan() {
  __shared__ int sw[8];
  int tid = threadIdx.x;
  int base = tid*8;
  int v[8], run = 0;
  #pragma unroll
  for (int i = 0; i < 8; i++) { v[i] = g_deg[base+i]; run += v[i]; }
  int lane = tid & 31, wid = tid >> 5;
  int incl = run;
  #pragma unroll
  for (int o = 1; o < 32; o <<= 1) {
    int u = __shfl_up_sync(0xffffffffu, incl, o);
    if (lane >= o) incl += u;
  }
  if (lane == 31) sw[wid] = incl;
  __syncthreads();
  if (tid == 0) {
    int acc = 0;
    #pragma unroll
    for (int w = 0; w < 8; w++) { int x = sw[w]; sw[w] = acc; acc += x; }
  }
  __syncthreads();
  int off = sw[wid] + incl - run;
  #pragma unroll
  for (int i = 0; i < 8; i++) {
    g_off[base+i] = off; g_cur[base+i] = off;
    off += v[i];
    g_deg[base+i] = 0;
  }
  if (tid == 0) g_off[2048] = Ee;
}

// ---------------- shared GEMM tile macros ----------------
#define GEMM_SMEM_DECL \
  __shared__ __align__(16) float As[2][32][68]; \
  __shared__ __align__(16) float Bs[2][32][68];

#define LDG_CHUNK(k0)                                                        \
    ra0 = *(const float4*)&A[(m0+lr)*lda + (k0) + ca];                       \
    ra1 = *(const float4*)&A[(m0+lr+32)*lda + (k0) + ca];                    \
    rb0 = (rn0 < Ncols) ? *(const float4*)&B[rn0*ldb + (k0) + ca] : z4;      \
    rb1 = (rn1 < Ncols) ? *(const float4*)&B[rn1*ldb + (k0) + ca] : z4;

#define STS_CHUNK(buf)                                                      \
    As[buf][ca+0][lr] = ra0.x; As[buf][ca+1][lr] = ra0.y;                    \
    As[buf][ca+2][lr] = ra0.z; As[buf][ca+3][lr] = ra0.w;                    \
    As[buf][ca+0][lr+32] = ra1.x; As[buf][ca+1][lr+32] = ra1.y;              \
    As[buf][ca+2][lr+32] = ra1.z; As[buf][ca+3][lr+32] = ra1.w;              \
    Bs[buf][ca+0][lr] = rb0.x; Bs[buf][ca+1][lr] = rb0.y;                    \
    Bs[buf][ca+2][lr] = rb0.z; Bs[buf][ca+3][lr] = rb0.w;                    \
    Bs[buf][ca+0][lr+32] = rb1.x; Bs[buf][ca+1][lr+32] = rb1.y;              \
    Bs[buf][ca+2][lr+32] = rb1.z; Bs[buf][ca+3][lr+32] = rb1.w;

#define GEMM_MAIN(Kv)                                                        \
  float acc[4][4] = {};                                                      \
  {                                                                          \
    int nc = (Kv)/32;                                                        \
    LDG_CHUNK(0); STS_CHUNK(0);                                              \
    __syncthreads();                                                         \
    for (int c = 0; c < nc; c++) {                                           \
      if (c+1 < nc) { LDG_CHUNK((c+1)*32); }                                 \
      int buf = c & 1;                                                       \
      _Pragma("unroll")                                                      \
      for (int k = 0; k < 32; k++) {                                         \
        float4 a4 = *(const float4*)&As[buf][k][ty*4];                       \
        float4 b4 = *(const float4*)&Bs[buf][k][tx*4];                       \
        acc[0][0] += a4.x*b4.x; acc[0][1] += a4.x*b4.y; acc[0][2] += a4.x*b4.z; acc[0][3] += a4.x*b4.w; \
        acc[1][0] += a4.y*b4.x; acc[1][1] += a4.y*b4.y; acc[1][2] += a4.y*b4.z; acc[1][3] += a4.y*b4.w; \
        acc[2][0] += a4.z*b4.x; acc[2][1] += a4.z*b4.y; acc[2][2] += a4.z*b4.z; acc[2][3] += a4.z*b4.w; \
        acc[3][0] += a4.w*b4.x; acc[3][1] += a4.w*b4.y; acc[3][2] += a4.w*b4.z; acc[3][3] += a4.w*b4.w; \
      }                                                                      \
      if (c+1 < nc) { STS_CHUNK((c+1)&1); }                                  \
      __syncthreads();                                                       \
    }                                                                        \
  }

// ---------------- double-buffered 64x64 GEMM kernel ----------------
// splitXr: route output column 128 to g_xr
template<int ACT>
__global__ void __launch_bounds__(256)
k_gemm(int Asel, int aoff, int lda, int Bsel, const float* __restrict__ Bext, int ldb,
       const float* __restrict__ bias, int Csel, int coff, int ldc,
       int Ncols, int K, int nMt, int ntiles, int withScan, int splitXr) {
  if (withScan && (int)blockIdx.x == ntiles) { dev_scan(); return; }
  if ((int)blockIdx.x >= ntiles) return;
  GEMM_SMEM_DECL
  int koff = blockIdx.y * 64;
  const float* A = sel_ptr(Asel) + aoff + koff;
  const float* B = (Bsel >= 0 ? sel_ptr(Bsel) : Bext) + koff;
  float* C = sel_ptr(Csel) + coff;
  int tid = threadIdx.x;
  int tx = tid & 15, ty = tid >> 4;
  int tile = blockIdx.x;
  int m0 = (tile % nMt)*64, n0 = (tile / nMt)*64;
  int lr = tid >> 3;            // 0..31
  int ca = (tid & 7)*4;
  int rn0 = n0 + lr, rn1 = rn0 + 32;
  float4 ra0, ra1, rb0, rb1;
  const float4 z4 = make_float4(0.f,0.f,0.f,0.f);
  GEMM_MAIN(K)
  #pragma unroll
  for (int i = 0; i < 4; i++) {
    int mm = m0 + ty*4 + i;
    #pragma unroll
    for (int j = 0; j < 4; j++) {
      int nn = n0 + tx*4 + j;
      if (nn < Ncols) {
        float v = acc[i][j];
        if (bias) v += bias[nn];
        if (ACT) v = fmaxf(v, 0.f);
        if (splitXr && nn == 128) g_xr[mm] = v;
        else C[mm*ldc + nn] = v;
      }
    }
  }
}

// ---------------- fused h2-GEMM + ab-GEMM ----------------
// Block = one 64-row tile. Phase 1: h2 = relu(lin2@S + bias) -> g_feat cols
// 192..319 (two 64x64 n-subtiles). Phase 2: ab tile = feat @ W1p^T (K=320,
// h2 part L1-hot, same rows just written by this block).
__global__ void __launch_bounds__(256)
k_h2ab(const float* __restrict__ lin2, const float* __restrict__ bias) {
  GEMM_SMEM_DECL
  int tid = threadIdx.x;
  int tx = tid & 15, ty = tid >> 4;
  int lr = tid >> 3;
  int ca = (tid & 7)*4;
  const float4 z4 = make_float4(0.f,0.f,0.f,0.f);
  int m0 = blockIdx.x*64;
  float4 ra0, ra1, rb0, rb1;

  // ---- phase 1: h2, two n-subtiles ----
  #pragma unroll
  for (int t = 0; t < 2; t++) {
    int n0 = t*64;
    const float* A = g_S;      int lda = 128;
    const float* B = lin2;     int ldb = 128;
    int Ncols = 128;
    int rn0 = n0 + lr, rn1 = rn0 + 32;
    __syncthreads();
    GEMM_MAIN(128)
    #pragma unroll
    for (int i = 0; i < 4; i++) {
      int mm = m0 + ty*4 + i;
      #pragma unroll
      for (int j = 0; j < 4; j++) {
        int nn = n0 + tx*4 + j;
        float v = fmaxf(acc[i][j] + bias[nn], 0.f);
        g_feat[mm*320 + 192 + nn] = v;
      }
    }
  }
  __syncthreads();   // h2 global writes visible block-wide

  // ---- phase 2: ab tile (64 x 40, K = 320) ----
  {
    int n0 = 0;
    const float* A = g_feat;   int lda = 320;
    const float* B = g_W1p;    int ldb = 320;
    int Ncols = 40;
    int rn0 = n0 + lr, rn1 = rn0 + 32;
    GEMM_MAIN(320)
    #pragma unroll
    for (int i = 0; i < 4; i++) {
      int mm = m0 + ty*4 + i;
      #pragma unroll
      for (int j = 0; j < 4; j++) {
        int nn = n0 + tx*4 + j;
        if (nn < Ncols) g_ab[mm*40 + nn] = acc[i][j];
      }
    }
  }
}

// ---------------- CSR scatter with combined payload ----------------
__global__ void k_scatter(const int* __restrict__ esrc, const int* __restrict__ edst,
                          const float* __restrict__ eattr) {
  int e = blockIdx.x*256 + threadIdx.x;
  int p = atomicAdd(&g_cur[edst[e]], 1);
  g_edge[p] = make_float2(__int_as_float(esrc[e]), eattr[e]);
}

// ---------------- 4-warps-per-node aggregation (R9 structure) ----------------
// Block = 8 warps = 2 nodes. Each of a node's 4 warps: strided quarter of the
// edge list, ILP-4 chunks; one barrier combines 4 partials. Grid 1024.
__global__ void __launch_bounds__(256)
k_aggr(int w1off, const float* __restrict__ attl) {
  int tid = threadIdx.x;
  int w = tid >> 5, lane = tid & 31;
  int half = w >> 2;                 // 0 or 1: which node of this block
  int wi   = w & 3;                  // warp index within the node group
  int n = blockIdx.x*2 + half;
  int begin = g_off[n], cnt = g_off[n+1] - begin;
  const float4* xw4 = (const float4*)g_xW;
  float4 wv = ((const float4*)(g_w1e + w1off))[lane];
  float4 av = ((const float4*)attl)[lane];
  float xr = g_xr[n];
  float ax=0.f, ay=0.f, az=0.f, aw=0.f, den=0.f;
  for (int j0 = wi*4; j0 < cnt; j0 += 16) {
    int nv = cnt - j0; if (nv > 4) nv = 4;
    float2 ee[4]; float4 xx[4];
    float hx[4], hy[4], hz[4], hw[4], pp[4];
    #pragma unroll
    for (int u = 0; u < 4; u++) if (u < nv) ee[u] = g_edge[begin + j0 + u];   // broadcast
    #pragma unroll
    for (int u = 0; u < 4; u++) if (u < nv) xx[u] = xw4[__float_as_int(ee[u].x)*32 + lane];
    #pragma unroll
    for (int u = 0; u < 4; u++) {
      if (u < nv) {
        float ea = ee[u].y;
        hx[u] = lrelu(xx[u].x + ea*wv.x);
        hy[u] = lrelu(xx[u].y + ea*wv.y);
        hz[u] = lrelu(xx[u].z + ea*wv.z);
        hw[u] = lrelu(xx[u].w + ea*wv.w);
        pp[u] = hx[u]*av.x + hy[u]*av.y + hz[u]*av.z + hw[u]*av.w;
      } else pp[u] = 0.f;
    }
    #pragma unroll
    for (int s = 16; s > 0; s >>= 1) {
      #pragma unroll
      for (int u = 0; u < 4; u++) pp[u] += __shfl_xor_sync(0xffffffffu, pp[u], s);
    }
    #pragma unroll
    for (int u = 0; u < 4; u++) if (u < nv) {
      float ev = __expf(lrelu(pp[u] + xr));
      ax += ev*hx[u]; ay += ev*hy[u]; az += ev*hz[u]; aw += ev*hw[u];
      den += ev;
    }
  }
  __shared__ float4 red4[8][32];
  __shared__ float dred[8];
  red4[w][lane] = make_float4(ax, ay, az, aw);
  if (lane == 0) dred[w] = den;
  __syncthreads();
  if (wi == 0) {                     // warps 0 and 4 finalize their node
    float4 r = red4[w][lane];
    float d = dred[w];
    #pragma unroll
    for (int s = 1; s < 4; s++) {
      float4 o = red4[w+s][lane];
      r.x += o.x; r.y += o.y; r.z += o.z; r.w += o.w;
      d += dred[w+s];
    }
    float inv = 1.f/(d + 1e-16f);
    ((float4*)g_S)[n*32 + lane] = make_float4(r.x*inv, r.y*inv, r.z*inv, r.w*inv);
  }
}

// ---------------- fused pairwise MLP + masked row softmax (f32x2, reg logits) -
__global__ void __launch_bounds__(256)
k_final(const float* __restrict__ b1, const float* __restrict__ W2,
        const float* __restrict__ b2, const float* __restrict__ m,
        float* __restrict__ out) {
  __shared__ unsigned long long ash2[8][10];       // packed (a+b1) col pairs
  __shared__ unsigned long long w2sh[10];
  __shared__ float rowM[8], rowInv[8];
  __shared__ __align__(16) float btile[256][22];   // stride 22 -> aligned b64; reused for reduce
  int tid = threadIdx.x;
  int i0 = blockIdx.x * 8;
  if (tid < 80) {
    int r = tid/10, cp = tid - r*10;
    float a0 = g_ab[(i0+r)*40 + 2*cp]   + b1[2*cp];
    float a1 = g_ab[(i0+r)*40 + 2*cp+1] + b1[2*cp+1];
    asm("mov.b64 %0, {%1, %2};" : "=l"(ash2[r][cp]) : "f"(a0), "f"(a1));
  }
  if (tid < 10) {
    asm("mov.b64 %0, {%1, %2};" : "=l"(w2sh[tid]) : "f"(W2[2*tid]), "f"(W2[2*tid+1]));
  }
  float b2v = b2[0];
  float lreg[8][8];                                // [tile][row] raw logits
  float omax[8], osum[8];
  #pragma unroll
  for (int r = 0; r < 8; r++) { omax[r] = -1e30f; osum[r] = 0.f; }
  __syncthreads();
  unsigned long long wr[10];
  #pragma unroll
  for (int cp = 0; cp < 10; cp++) wr[cp] = w2sh[cp];

  #pragma unroll
  for (int t = 0; t < 8; t++) {
    int jt = t*256;
    __syncthreads();
    #pragma unroll
    for (int u = 0; u < 20; u++) {
      int l = u*256 + tid;
      int tt = l / 20, c = l - tt*20;
      btile[tt][c] = g_ab[(jt+tt)*40 + 20 + c];
    }
    __syncthreads();
    unsigned long long bl2[10];
    #pragma unroll
    for (int cp = 0; cp < 10; cp++)
      bl2[cp] = *(const unsigned long long*)&btile[tid][2*cp];
    int j = jt + tid;
    #pragma unroll
    for (int r = 0; r < 8; r++) {
      unsigned long long acc2 = 0ULL;      // (0.f, 0.f)
      #pragma unroll
      for (int cp = 0; cp < 10; cp++) {
        unsigned long long s;
        asm("add.rn.f32x2 %0, %1, %2;" : "=l"(s) : "l"(ash2[r][cp]), "l"(bl2[cp]));
        float lo, hi;
        asm("mov.b64 {%0, %1}, %2;" : "=f"(lo), "=f"(hi) : "l"(s));
        lo = fmaxf(lo, 0.f); hi = fmaxf(hi, 0.f);
        asm("mov.b64 %0, {%1, %2};" : "=l"(s) : "f"(lo), "f"(hi));
        asm("fma.rn.f32x2 %0, %1, %2, %3;" : "=l"(acc2) : "l"(s), "l"(wr[cp]), "l"(acc2));
      }
      float alo, ahi;
      asm("mov.b64 {%0, %1}, %2;" : "=f"(alo), "=f"(ahi) : "l"(acc2));
      float lv = (alo + ahi + b2v) * m[(size_t)(i0+r)*Nn + j];
      lreg[t][r] = lv;
      float nm = fmaxf(omax[r], lv);
      osum[r] = osum[r]*__expf(omax[r]-nm) + __expf(lv-nm);
      omax[r] = nm;
    }
  }
  // (max,sum) merge: smem transpose + warp reduction (2 syncs)
  __syncthreads();
  float2* pr = (float2*)btile;
  #pragma unroll
  for (int r = 0; r < 8; r++) pr[r*256 + tid] = make_float2(omax[r], osum[r]);
  __syncthreads();
  int w = tid >> 5, lane = tid & 31;
  if (w < 8) {
    float M = -1e30f, S = 0.f;
    #pragma unroll
    for (int i = 0; i < 8; i++) {
      float2 v = pr[w*256 + lane + i*32];
      float nm = fmaxf(M, v.x);
      S = S*__expf(M-nm) + v.y*__expf(v.x-nm);
      M = nm;
    }
    #pragma unroll
    for (int s = 16; s > 0; s >>= 1) {
      float oM = __shfl_xor_sync(0xffffffffu, M, s);
      float oS = __shfl_xor_sync(0xffffffffu, S, s);
      float nm = fmaxf(M, oM);
      S = S*__expf(M-nm) + oS*__expf(oM-nm);
      M = nm;
    }
    if (lane == 0) { rowM[w] = M; rowInv[w] = 1.f/S; }
  }
  __syncthreads();
  #pragma unroll
  for (int t = 0; t < 8; t++) {
    int j = t*256 + tid;
    #pragma unroll
    for (int r = 0; r < 8; r++) {
      out[(size_t)(i0+r)*Nn + j] = __expf(lreg[t][r] - rowM[r]) * rowInv[r];
    }
  }
}

// ---------------- driver ----------------
extern "C" void kernel_launch(void* const* d_in, const int* in_sizes, int n_in,
                              void* d_out, int out_size) {
  const int*   node_ids = (const int*)  d_in[0];
  const int*   eidx     = (const int*)  d_in[1];
  const float* eattr    = (const float*)d_in[2];
  const float* m        = (const float*)d_in[3];
  const float* emb      = (const float*)d_in[4];
  const float* l0_lin1  = (const float*)d_in[5];
  const float* l0_lin2  = (const float*)d_in[6];
  const float* l0_attl  = (const float*)d_in[7];
  const float* l0_attr  = (const float*)d_in[8];
  const float* l0_bias  = (const float*)d_in[9];
  const float* l1_lin1  = (const float*)d_in[10];
  const float* l1_lin2  = (const float*)d_in[11];
  const float* l1_attl  = (const float*)d_in[12];
  const float* l1_attr  = (const float*)d_in[13];
  const float* l1_bias  = (const float*)d_in[14];
  const float* W1       = (const float*)d_in[15];
  const float* b1       = (const float*)d_in[16];
  const float* W2       = (const float*)d_in[17];
  const float* b2       = (const float*)d_in[18];
  float* out = (float*)d_out;
  const int* esrc = eidx;
  const int* edst = eidx + Ee;

  k_setup<<<534, 256>>>(node_ids, emb, W1, l0_lin1, l1_lin1, l0_attr, l1_attr, edst);

  // xW0 (96 tiles, col 128 -> g_xr) + CSR scan (block 96)
  k_gemm<0><<<97, 256>>>(0, 0, 320, 4, nullptr, 64, nullptr, 2, 0, 128,
                         129, 64, 32, 96, 1, 1);
  k_scatter<<<Ee/256, 256>>>(esrc, edst, eattr);
  k_aggr<<<Nn/2, 256>>>(0, l0_attl);
  k_gemm<1><<<64, 256>>>(1, 0, 128, -1, l0_lin2, 128, l0_bias, 0, 64, 320,
                         128, 128, 32, 64, 0, 0);         // h1 -> feat cols 64..191
  k_gemm<0><<<96, 256>>>(0, 64, 320, 5, nullptr, 128, nullptr, 2, 0, 128,
                         129, 128, 32, 96, 0, 1);         // xW1 (col 128 -> g_xr)
  k_aggr<<<Nn/2, 256>>>(128, l1_attl);
  k_h2ab<<<32, 256>>>(l1_lin2, l1_bias);                  // h2 -> feat, then ab
  k_final<<<Nn/8, 256>>>(b1, W2, b2, m, out);
}

// round 15
// speedup vs baseline: 1.0861x; 1.0861x over previous
#include <cuda_runtime.h>

#define Nn 2048
#define Ee 65536

// ---------------- scratch (device globals; no allocations) ----------------
__device__ __align__(16) float g_feat[Nn*320];     // [x | h1 | h2]
__device__ __align__(16) float g_xW[Nn*128];       // 512B line-aligned rows
__device__ __align__(16) float g_xr[Nn];
__device__ __align__(16) float g_S[Nn*128];
__device__ __align__(16) float g_ab[Nn*40];        // zeroed in setup (split-K atomics)
__device__ __align__(16) float g_W1p[40*320];
__device__ __align__(16) float g_B0p[129*64];
__device__ __align__(16) float g_B1p[129*128];
__device__ __align__(16) float g_w1e[256];
__device__ __align__(16) float2 g_edge[Ee];        // CSR payload: (src bits, edge_attr)
__device__ int g_deg[Nn];                          // invariant: zero (restored by scan)
__device__ int g_off[Nn+1];
__device__ int g_cur[Nn];

__device__ __forceinline__ float lrelu(float x) { return x > 0.f ? x : 0.01f*x; }

__device__ __forceinline__ float* sel_ptr(int s) {
  switch (s) {
    case 0: return g_feat;
    case 1: return g_S;
    case 2: return g_xW;
    case 3: return g_W1p;
    case 4: return g_B0p;
    case 5: return g_B1p;
    case 6: return g_ab;
    default: return nullptr;
  }
}

// ---------------- fused setup: embed(f4) + packs + hist + ab-zero ------------
__global__ void k_setup(const int* __restrict__ ids, const float* __restrict__ emb,
                        const float* __restrict__ W1,
                        const float* __restrict__ l0_lin1, const float* __restrict__ l1_lin1,
                        const float* __restrict__ l0_attr, const float* __restrict__ l1_attr,
                        const int* __restrict__ edst) {
  int b = blockIdx.x, tid = threadIdx.x;
  if (b < 128) {                       // embedding -> feat cols 0..63, float4
    int node = b*16 + (tid >> 4);
    int c4 = tid & 15;
    ((float4*)g_feat)[node*80 + c4] = ((const float4*)emb)[ids[node]*16 + c4];
  } else if (b < 178) {
    int i = (b-128)*256 + tid;
    if (i < 40*320) {
      int r = i/320, c = i - r*320;
      g_W1p[i] = (r < 20) ? W1[r*640 + c] : W1[(r-20)*640 + 320 + c];
    }
  } else if (b == 178) {
    if (tid < 128) {
      g_w1e[tid]       = l0_lin1[tid*65  + 64];
      g_w1e[128 + tid] = l1_lin1[tid*129 + 128];
    }
  } else if (b < 213) {
    int i = (b-179)*256 + tid;
    if (i < 129*64) {
      int r = i >> 6, c = i & 63;
      g_B0p[i] = (r < 128) ? l0_lin1[r*65 + c] : l0_attr[c];
    }
  } else if (b < 278) {
    int i = (b-213)*256 + tid;
    if (i < 129*128) {
      int r = i >> 7, c = i & 127;
      g_B1p[i] = (r < 128) ? l1_lin1[r*129 + c] : l1_attr[c];
    }
  } else if (b < 534) {
    int e = (b-278)*256 + tid;
    atomicAdd(&g_deg[edst[e]], 1);
  } else {
    g_ab[(b-534)*256 + tid] = 0.f;     // 320 blocks: 81920 floats
  }
}

// ---------------- scan (256 threads), restores g_deg=0 ----------------
__device__ void dev_scan() {
  __shared__ int sw[8];
  int tid = threadIdx.x;
  int base = tid*8;
  int v[8], run = 0;
  #pragma unroll
  for (int i = 0; i < 8; i++) { v[i] = g_deg[base+i]; run += v[i]; }
  int lane = tid & 31, wid = tid >> 5;
  int incl = run;
  #pragma unroll
  for (int o = 1; o < 32; o <<= 1) {
    int u = __shfl_up_sync(0xffffffffu, incl, o);
    if (lane >= o) incl += u;
  }
  if (lane == 31) sw[wid] = incl;
  __syncthreads();
  if (tid == 0) {
    int acc = 0;
    #pragma unroll
    for (int w = 0; w < 8; w++) { int x = sw[w]; sw[w] = acc; acc += x; }
  }
  __syncthreads();
  int off = sw[wid] + incl - run;
  #pragma unroll
  for (int i = 0; i < 8; i++) {
    g_off[base+i] = off; g_cur[base+i] = off;
    off += v[i];
    g_deg[base+i] = 0;
  }
  if (tid == 0) g_off[2048] = Ee;
}

// ---------------- shared GEMM tile macros ----------------
#define GEMM_SMEM_DECL \
  __shared__ __align__(16) float As[2][32][68]; \
  __shared__ __align__(16) float Bs[2][32][68];

#define LDG_CHUNK(k0)                                                        \
    ra0 = *(const float4*)&A[(m0+lr)*lda + (k0) + ca];                       \
    ra1 = *(const float4*)&A[(m0+lr+32)*lda + (k0) + ca];                    \
    rb0 = (rn0 < Ncols) ? *(const float4*)&B[rn0*ldb + (k0) + ca] : z4;      \
    rb1 = (rn1 < Ncols) ? *(const float4*)&B[rn1*ldb + (k0) + ca] : z4;

#define STS_CHUNK(buf)                                                      \
    As[buf][ca+0][lr] = ra0.x; As[buf][ca+1][lr] = ra0.y;                    \
    As[buf][ca+2][lr] = ra0.z; As[buf][ca+3][lr] = ra0.w;                    \
    As[buf][ca+0][lr+32] = ra1.x; As[buf][ca+1][lr+32] = ra1.y;              \
    As[buf][ca+2][lr+32] = ra1.z; As[buf][ca+3][lr+32] = ra1.w;              \
    Bs[buf][ca+0][lr] = rb0.x; Bs[buf][ca+1][lr] = rb0.y;                    \
    Bs[buf][ca+2][lr] = rb0.z; Bs[buf][ca+3][lr] = rb0.w;                    \
    Bs[buf][ca+0][lr+32] = rb1.x; Bs[buf][ca+1][lr+32] = rb1.y;              \
    Bs[buf][ca+2][lr+32] = rb1.z; Bs[buf][ca+3][lr+32] = rb1.w;

#define GEMM_MAIN(Kv)                                                        \
  float acc[4][4] = {};                                                      \
  {                                                                          \
    int nc = (Kv)/32;                                                        \
    LDG_CHUNK(0); STS_CHUNK(0);                                              \
    __syncthreads();                                                         \
    for (int c = 0; c < nc; c++) {                                           \
      if (c+1 < nc) { LDG_CHUNK((c+1)*32); }                                 \
      int buf = c & 1;                                                       \
      _Pragma("unroll")                                                      \
      for (int k = 0; k < 32; k++) {                                         \
        float4 a4 = *(const float4*)&As[buf][k][ty*4];                       \
        float4 b4 = *(const float4*)&Bs[buf][k][tx*4];                       \
        acc[0][0] += a4.x*b4.x; acc[0][1] += a4.x*b4.y; acc[0][2] += a4.x*b4.z; acc[0][3] += a4.x*b4.w; \
        acc[1][0] += a4.y*b4.x; acc[1][1] += a4.y*b4.y; acc[1][2] += a4.y*b4.z; acc[1][3] += a4.y*b4.w; \
        acc[2][0] += a4.z*b4.x; acc[2][1] += a4.z*b4.y; acc[2][2] += a4.z*b4.z; acc[2][3] += a4.z*b4.w; \
        acc[3][0] += a4.w*b4.x; acc[3][1] += a4.w*b4.y; acc[3][2] += a4.w*b4.z; acc[3][3] += a4.w*b4.w; \
      }                                                                      \
      if (c+1 < nc) { STS_CHUNK((c+1)&1); }                                  \
      __syncthreads();                                                       \
    }                                                                        \
  }

// ---------------- double-buffered 64x64 GEMM kernel ----------------
// splitXr: route output column 128 to g_xr; ATOMIC: split-K accumulation
template<int ACT, int ATOMIC>
__global__ void __launch_bounds__(256)
k_gemm(int Asel, int aoff, int lda, int Bsel, const float* __restrict__ Bext, int ldb,
       const float* __restrict__ bias, int Csel, int coff, int ldc,
       int Ncols, int K, int nMt, int ntiles, int withScan, int splitXr) {
  if (withScan && (int)blockIdx.x == ntiles) { dev_scan(); return; }
  if ((int)blockIdx.x >= ntiles) return;
  GEMM_SMEM_DECL
  int koff = blockIdx.y * 64;
  const float* A = sel_ptr(Asel) + aoff + koff;
  const float* B = (Bsel >= 0 ? sel_ptr(Bsel) : Bext) + koff;
  float* C = sel_ptr(Csel) + coff;
  int tid = threadIdx.x;
  int tx = tid & 15, ty = tid >> 4;
  int tile = blockIdx.x;
  int m0 = (tile % nMt)*64, n0 = (tile / nMt)*64;
  int lr = tid >> 3;            // 0..31
  int ca = (tid & 7)*4;
  int rn0 = n0 + lr, rn1 = rn0 + 32;
  float4 ra0, ra1, rb0, rb1;
  const float4 z4 = make_float4(0.f,0.f,0.f,0.f);
  GEMM_MAIN(K)
  #pragma unroll
  for (int i = 0; i < 4; i++) {
    int mm = m0 + ty*4 + i;
    #pragma unroll
    for (int j = 0; j < 4; j++) {
      int nn = n0 + tx*4 + j;
      if (nn < Ncols) {
        float v = acc[i][j];
        if (ATOMIC) {
          atomicAdd(&C[mm*ldc + nn], v);
        } else {
          if (bias) v += bias[nn];
          if (ACT) v = fmaxf(v, 0.f);
          if (splitXr && nn == 128) g_xr[mm] = v;
          else C[mm*ldc + nn] = v;
        }
      }
    }
  }
}

// ---------------- CSR scatter with combined payload ----------------
__global__ void k_scatter(const int* __restrict__ esrc, const int* __restrict__ edst,
                          const float* __restrict__ eattr) {
  int e = blockIdx.x*256 + threadIdx.x;
  int p = atomicAdd(&g_cur[edst[e]], 1);
  g_edge[p] = make_float2(__int_as_float(esrc[e]), eattr[e]);
}

// ---------------- 4-warps-per-node aggregation (R9 structure) ----------------
// Block = 8 warps = 2 nodes. Each of a node's 4 warps: strided quarter of the
// edge list, ILP-4 chunks; one barrier combines 4 partials. Grid 1024.
__global__ void __launch_bounds__(256)
k_aggr(int w1off, const float* __restrict__ attl) {
  int tid = threadIdx.x;
  int w = tid >> 5, lane = tid & 31;
  int half = w >> 2;                 // 0 or 1: which node of this block
  int wi   = w & 3;                  // warp index within the node group
  int n = blockIdx.x*2 + half;
  int begin = g_off[n], cnt = g_off[n+1] - begin;
  const float4* xw4 = (const float4*)g_xW;
  float4 wv = ((const float4*)(g_w1e + w1off))[lane];
  float4 av = ((const float4*)attl)[lane];
  float xr = g_xr[n];
  float ax=0.f, ay=0.f, az=0.f, aw=0.f, den=0.f;
  for (int j0 = wi*4; j0 < cnt; j0 += 16) {
    int nv = cnt - j0; if (nv > 4) nv = 4;
    float2 ee[4]; float4 xx[4];
    float hx[4], hy[4], hz[4], hw[4], pp[4];
    #pragma unroll
    for (int u = 0; u < 4; u++) if (u < nv) ee[u] = g_edge[begin + j0 + u];   // broadcast
    #pragma unroll
    for (int u = 0; u < 4; u++) if (u < nv) xx[u] = xw4[__float_as_int(ee[u].x)*32 + lane];
    #pragma unroll
    for (int u = 0; u < 4; u++) {
      if (u < nv) {
        float ea = ee[u].y;
        hx[u] = lrelu(xx[u].x + ea*wv.x);
        hy[u] = lrelu(xx[u].y + ea*wv.y);
        hz[u] = lrelu(xx[u].z + ea*wv.z);
        hw[u] = lrelu(xx[u].w + ea*wv.w);
        pp[u] = hx[u]*av.x + hy[u]*av.y + hz[u]*av.z + hw[u]*av.w;
      } else pp[u] = 0.f;
    }
    #pragma unroll
    for (int s = 16; s > 0; s >>= 1) {
      #pragma unroll
      for (int u = 0; u < 4; u++) pp[u] += __shfl_xor_sync(0xffffffffu, pp[u], s);
    }
    #pragma unroll
    for (int u = 0; u < 4; u++) if (u < nv) {
      float ev = __expf(lrelu(pp[u] + xr));
      ax += ev*hx[u]; ay += ev*hy[u]; az += ev*hz[u]; aw += ev*hw[u];
      den += ev;
    }
  }
  __shared__ float4 red4[8][32];
  __shared__ float dred[8];
  red4[w][lane] = make_float4(ax, ay, az, aw);
  if (lane == 0) dred[w] = den;
  __syncthreads();
  if (wi == 0) {                     // warps 0 and 4 finalize their node
    float4 r = red4[w][lane];
    float d = dred[w];
    #pragma unroll
    for (int s = 1; s < 4; s++) {
      float4 o = red4[w+s][lane];
      r.x += o.x; r.y += o.y; r.z += o.z; r.w += o.w;
      d += dred[w+s];
    }
    float inv = 1.f/(d + 1e-16f);
    ((float4*)g_S)[n*32 + lane] = make_float4(r.x*inv, r.y*inv, r.z*inv, r.w*inv);
  }
}

// ---------------- fused pairwise MLP + masked row softmax (f32x2, reg logits) -
__global__ void __launch_bounds__(256)
k_final(const float* __restrict__ b1, const float* __restrict__ W2,
        const float* __restrict__ b2, const float* __restrict__ m,
        float* __restrict__ out) {
  __shared__ unsigned long long ash2[8][10];       // packed (a+b1) col pairs
  __shared__ unsigned long long w2sh[10];
  __shared__ float rowM[8], rowInv[8];
  __shared__ __align__(16) float btile[256][22];   // stride 22 -> aligned b64; reused for reduce
  int tid = threadIdx.x;
  int i0 = blockIdx.x * 8;
  if (tid < 80) {
    int r = tid/10, cp = tid - r*10;
    float a0 = g_ab[(i0+r)*40 + 2*cp]   + b1[2*cp];
    float a1 = g_ab[(i0+r)*40 + 2*cp+1] + b1[2*cp+1];
    asm("mov.b64 %0, {%1, %2};" : "=l"(ash2[r][cp]) : "f"(a0), "f"(a1));
  }
  if (tid < 10) {
    asm("mov.b64 %0, {%1, %2};" : "=l"(w2sh[tid]) : "f"(W2[2*tid]), "f"(W2[2*tid+1]));
  }
  float b2v = b2[0];
  float lreg[8][8];                                // [tile][row] raw logits
  float omax[8], osum[8];
  #pragma unroll
  for (int r = 0; r < 8; r++) { omax[r] = -1e30f; osum[r] = 0.f; }
  __syncthreads();
  unsigned long long wr[10];
  #pragma unroll
  for (int cp = 0; cp < 10; cp++) wr[cp] = w2sh[cp];

  #pragma unroll
  for (int t = 0; t < 8; t++) {
    int jt = t*256;
    __syncthreads();
    #pragma unroll
    for (int u = 0; u < 20; u++) {
      int l = u*256 + tid;
      int tt = l / 20, c = l - tt*20;
      btile[tt][c] = g_ab[(jt+tt)*40 + 20 + c];
    }
    __syncthreads();
    unsigned long long bl2[10];
    #pragma unroll
    for (int cp = 0; cp < 10; cp++)
      bl2[cp] = *(const unsigned long long*)&btile[tid][2*cp];
    int j = jt + tid;
    #pragma unroll
    for (int r = 0; r < 8; r++) {
      unsigned long long acc2 = 0ULL;      // (0.f, 0.f)
      #pragma unroll
      for (int cp = 0; cp < 10; cp++) {
        unsigned long long s;
        asm("add.rn.f32x2 %0, %1, %2;" : "=l"(s) : "l"(ash2[r][cp]), "l"(bl2[cp]));
        float lo, hi;
        asm("mov.b64 {%0, %1}, %2;" : "=f"(lo), "=f"(hi) : "l"(s));
        lo = fmaxf(lo, 0.f); hi = fmaxf(hi, 0.f);
        asm("mov.b64 %0, {%1, %2};" : "=l"(s) : "f"(lo), "f"(hi));
        asm("fma.rn.f32x2 %0, %1, %2, %3;" : "=l"(acc2) : "l"(s), "l"(wr[cp]), "l"(acc2));
      }
      float alo, ahi;
      asm("mov.b64 {%0, %1}, %2;" : "=f"(alo), "=f"(ahi) : "l"(acc2));
      float lv = (alo + ahi + b2v) * m[(size_t)(i0+r)*Nn + j];
      lreg[t][r] = lv;
      float nm = fmaxf(omax[r], lv);
      osum[r] = osum[r]*__expf(omax[r]-nm) + __expf(lv-nm);
      omax[r] = nm;
    }
  }
  // (max,sum) merge: smem transpose + warp reduction (2 syncs)
  __syncthreads();
  float2* pr = (float2*)btile;
  #pragma unroll
  for (int r = 0; r < 8; r++) pr[r*256 + tid] = make_float2(omax[r], osum[r]);
  __syncthreads();
  int w = tid >> 5, lane = tid & 31;
  if (w < 8) {
    float M = -1e30f, S = 0.f;
    #pragma unroll
    for (int i = 0; i < 8; i++) {
      float2 v = pr[w*256 + lane + i*32];
      float nm = fmaxf(M, v.x);
      S = S*__expf(M-nm) + v.y*__expf(v.x-nm);
      M = nm;
    }
    #pragma unroll
    for (int s = 16; s > 0; s >>= 1) {
      float oM = __shfl_xor_sync(0xffffffffu, M, s);
      float oS = __shfl_xor_sync(0xffffffffu, S, s);
      float nm = fmaxf(M, oM);
      S = S*__expf(M-nm) + oS*__expf(oM-nm);
      M = nm;
    }
    if (lane == 0) { rowM[w] = M; rowInv[w] = 1.f/S; }
  }
  __syncthreads();
  #pragma unroll
  for (int t = 0; t < 8; t++) {
    int j = t*256 + tid;
    #pragma unroll
    for (int r = 0; r < 8; r++) {
      out[(size_t)(i0+r)*Nn + j] = __expf(lreg[t][r] - rowM[r]) * rowInv[r];
    }
  }
}

// ---------------- driver ----------------
extern "C" void kernel_launch(void* const* d_in, const int* in_sizes, int n_in,
                              void* d_out, int out_size) {
  const int*   node_ids = (const int*)  d_in[0];
  const int*   eidx     = (const int*)  d_in[1];
  const float* eattr    = (const float*)d_in[2];
  const float* m        = (const float*)d_in[3];
  const float* emb      = (const float*)d_in[4];
  const float* l0_lin1  = (const float*)d_in[5];
  const float* l0_lin2  = (const float*)d_in[6];
  const float* l0_attl  = (const float*)d_in[7];
  const float* l0_attr  = (const float*)d_in[8];
  const float* l0_bias  = (const float*)d_in[9];
  const float* l1_lin1  = (const float*)d_in[10];
  const float* l1_lin2  = (const float*)d_in[11];
  const float* l1_attl  = (const float*)d_in[12];
  const float* l1_attr  = (const float*)d_in[13];
  const float* l1_bias  = (const float*)d_in[14];
  const float* W1       = (const float*)d_in[15];
  const float* b1       = (const float*)d_in[16];
  const float* W2       = (const float*)d_in[17];
  const float* b2       = (const float*)d_in[18];
  float* out = (float*)d_out;
  const int* esrc = eidx;
  const int* edst = eidx + Ee;

  k_setup<<<854, 256>>>(node_ids, emb, W1, l0_lin1, l1_lin1, l0_attr, l1_attr, edst);

  // xW0 (96 tiles, col 128 -> g_xr) + CSR scan (block 96)
  k_gemm<0,0><<<97, 256>>>(0, 0, 320, 4, nullptr, 64, nullptr, 2, 0, 128,
                           129, 64, 32, 96, 1, 1);
  k_scatter<<<Ee/256, 256>>>(esrc, edst, eattr);
  k_aggr<<<Nn/2, 256>>>(0, l0_attl);
  k_gemm<1,0><<<64, 256>>>(1, 0, 128, -1, l0_lin2, 128, l0_bias, 0, 64, 320,
                           128, 128, 32, 64, 0, 0);       // h1 -> feat cols 64..191
  k_gemm<0,0><<<96, 256>>>(0, 64, 320, 5, nullptr, 128, nullptr, 2, 0, 128,
                           129, 128, 32, 96, 0, 1);       // xW1 (col 128 -> g_xr)
  k_aggr<<<Nn/2, 256>>>(128, l1_attl);
  k_gemm<1,0><<<64, 256>>>(1, 0, 128, -1, l1_lin2, 128, l1_bias, 0, 192, 320,
                           128, 128, 32, 64, 0, 0);       // h2 -> feat cols 192..319
  // ab split-K: grid (32 Mtiles, 5 K-chunks), atomicAdd into zeroed g_ab
  k_gemm<0,1><<<dim3(32, 5), 256>>>(0, 0, 320, 3, nullptr, 320, nullptr, 6, 0, 40,
                                    40, 64, 32, 32, 0, 0);
  k_final<<<Nn/8, 256>>>(b1, W2, b2, m, out);
}